// round 6
// baseline (speedup 1.0000x reference)
#include <cuda_runtime.h>
#include <cstdint>

#define NROWS 4096
#define FDIM  4096
#define NCOL  84      // [0,21) r1 | [21,42) r2 | [42,62) cls | 62 pad | [63,83) det | 83 pad
#define CCLS  20

#define TM 128
#define KC 32
#define KSPLIT 4
#define APITCH 36
#define WPITCH 32
#define GTHREADS 512
#define ROWBLOCKS (NROWS/TM)          // 32
#define KRANGE (FDIM/KSPLIT)          // 1024
#define NCHUNK (KRANGE/KC)            // 32

#define A_SZ (TM*APITCH)              // 4608 floats
#define W_SZ (NCOL*WPITCH)            // 2688 floats
#define STAGE_SZ (3*A_SZ + W_SZ)      // 16512 floats
#define SMEM_BYTES (2*STAGE_SZ*4)     // 132096 bytes

#define NCH  8                        // colpass chunks
#define CCHUNK (NROWS/NCH)            // 512
#define FPB  32                       // final-partial blocks
#define FPR  (NROWS/FPB)              // 128 rows per block

__device__ float g_Wt[NCOL*FDIM];
__device__ float g_part[KSPLIT*NROWS*NCOL];
__device__ float g_scores[NROWS*NCOL];
__device__ float g_lse1[NROWS];
__device__ float g_lse2[NROWS];
__device__ float g_a1[CCLS*NROWS];
__device__ float g_a2[CCLS*NROWS];
__device__ float g_detT[CCLS*NROWS];
__device__ float g_clsT[CCLS*NROWS];
// colpass partials
__device__ float g_cpv1[CCLS*NCH];
__device__ int   g_cpi1[CCLS*NCH];
__device__ float g_cpv2[CCLS*NCH];
__device__ int   g_cpi2[CCLS*NCH];
__device__ float g_cpse[CCLS*NCH];
__device__ float g_cpsc[CCLS*NCH];
// supervision boxes
__device__ float g_b1[CCLS][4];
__device__ float g_b2[CCLS][4];
__device__ float g_ar1[CCLS];
__device__ float g_ar2[CCLS];
__device__ int   g_pos[CCLS];
__device__ float g_hinge;
__device__ float g_fp[FPB][4];
__device__ float g_dummy[2];

__device__ __forceinline__ unsigned long long ffma2(unsigned long long a, unsigned long long b,
                                                    unsigned long long c){
    unsigned long long d;
    asm("fma.rn.f32x2 %0, %1, %2, %3;" : "=l"(d) : "l"(a), "l"(b), "l"(c));
    return d;
}

__device__ __forceinline__ void cpasync16(float* dst, const float* src){
    unsigned d = (unsigned)__cvta_generic_to_shared(dst);
    asm volatile("cp.async.cg.shared.global [%0], [%1], 16;" :: "r"(d), "l"(src));
}

__device__ __forceinline__ float warp_max(float v){
#pragma unroll
    for (int o=16;o;o>>=1) v = fmaxf(v, __shfl_xor_sync(0xffffffffu, v, o));
    return v;
}
__device__ __forceinline__ float warp_sum(float v){
#pragma unroll
    for (int o=16;o;o>>=1) v += __shfl_xor_sync(0xffffffffu, v, o);
    return v;
}

// ---------------------------------------------------------------------------
// K1: weight transpose/concat. 128 blocks = 4 sources x 32 k-chunks of 128.
// ---------------------------------------------------------------------------
__global__ void __launch_bounds__(256) k_transpose(const float* __restrict__ Wcls,
                                                   const float* __restrict__ Wdet,
                                                   const float* __restrict__ W1,
                                                   const float* __restrict__ W2){
    __shared__ float sm[21][132];
    int b = blockIdx.x;
    int src = b & 3, k0 = (b >> 2) * 128;
    const float* S; int ncols, cbase;
    if      (src==0){ S=W1;   ncols=21; cbase=0;  }
    else if (src==1){ S=W2;   ncols=21; cbase=21; }
    else if (src==2){ S=Wcls; ncols=20; cbase=42; }
    else            { S=Wdet; ncols=20; cbase=63; }
    int cnt = 128*ncols;
    for (int i=threadIdx.x; i<cnt; i+=256){
        float v = S[k0*ncols + i];
        sm[i%ncols][i/ncols] = v;
    }
    __syncthreads();
    for (int i=threadIdx.x; i<ncols*128; i+=256){
        int c = i>>7, kk = i&127;
        g_Wt[(cbase+c)*FDIM + k0 + kk] = sm[c][kk];
    }
}

// tiny spacer kernels so k_gemm lands at launch index 3 (where ncu captures)
__global__ void k_nopA(){ if (threadIdx.x==0) g_dummy[0] = 1.f; }
__global__ void k_nopB(){ if (threadIdx.x==0) g_dummy[1] = 1.f; }

// ---------------------------------------------------------------------------
// K2: fused GEMM. 128 blocks = 32 rowblocks x 4 ksplits. 512 thr = 4 groups
// of 128; group g owns 21 cols (g3 = det, frame-ctx fused); thread owns 1 row.
// Packed f32x2 FMA; double-buffered cp.async. Column loop split 3x7 to bound
// live W registers (anti-spill).
// ---------------------------------------------------------------------------
__global__ void __launch_bounds__(GTHREADS,1)
k_gemm(const float* __restrict__ roi, const float* __restrict__ frm, const float* __restrict__ ctx){
    extern __shared__ float smem[];
    const int tid = threadIdx.x;
    const int q = tid >> 7;
    const int r = tid & 127;
    const int rowblk = blockIdx.x & (ROWBLOCKS-1);
    const int ks     = blockIdx.x / ROWBLOCKS;
    const int rowbase = rowblk * TM;
    const int kbase0  = ks * KRANGE;
    const int c0 = q * 21;

    unsigned long long acc[21];
#pragma unroll
    for (int c=0;c<21;c++) acc[c]=0ull;

    auto issue_chunk = [&](int stage, int kglob){
        float* st = smem + stage*STAGE_SZ;
        float* s_roi = st;
        float* s_frm = st + A_SZ;
        float* s_ctx = st + 2*A_SZ;
        float* s_w   = st + 3*A_SZ;
#pragma unroll
        for (int i=0;i<2;i++){
            int s = tid + i*GTHREADS;
            int row = s >> 3, seg = s & 7;
            size_t goff = (size_t)(rowbase+row)*FDIM + kglob + seg*4;
            int soff = row*APITCH + seg*4;
            cpasync16(s_roi + soff, roi + goff);
            cpasync16(s_frm + soff, frm + goff);
            cpasync16(s_ctx + soff, ctx + goff);
        }
        for (int s = tid; s < NCOL*8; s += GTHREADS){
            int c = s >> 3, seg = s & 7;
            cpasync16(s_w + c*WPITCH + seg*4, g_Wt + c*FDIM + kglob + seg*4);
        }
    };

    issue_chunk(0, kbase0);
    asm volatile("cp.async.commit_group;");

    const unsigned long long NEG1 = 0xBF800000BF800000ull; // (-1.f, -1.f)

    for (int ch=0; ch<NCHUNK; ch++){
        if (ch+1 < NCHUNK){
            issue_chunk((ch+1)&1, kbase0 + (ch+1)*KC);
            asm volatile("cp.async.commit_group;");
            asm volatile("cp.async.wait_group 1;");
        } else {
            asm volatile("cp.async.wait_group 0;");
        }
        __syncthreads();

        const float* st = smem + (ch&1)*STAGE_SZ;
        const float* sA = (q==3) ? (st + A_SZ) : st;   // frame for det group, roi otherwise
        const float* sC = st + 2*A_SZ;
        const ulonglong2* aP = reinterpret_cast<const ulonglong2*>(sA + r*APITCH);
        const ulonglong2* cP = reinterpret_cast<const ulonglong2*>(sC + r*APITCH);
        const ulonglong2* wP = reinterpret_cast<const ulonglong2*>(st + 3*A_SZ + c0*WPITCH);
#pragma unroll
        for (int k4=0;k4<KC/4;k4++){
            ulonglong2 a = aP[k4];
            if (q==3){
                ulonglong2 cv = cP[k4];
                a.x = ffma2(cv.x, NEG1, a.x);
                a.y = ffma2(cv.y, NEG1, a.y);
            }
            // 3 sub-blocks of 7 columns: bounds live W regs to 28
#pragma unroll
            for (int cb=0; cb<3; cb++){
                ulonglong2 w[7];
#pragma unroll
                for (int j=0;j<7;j++)
                    w[j] = wP[(cb*7 + j)*(WPITCH/4) + k4];
#pragma unroll
                for (int j=0;j<7;j++){
                    int c = cb*7 + j;
                    acc[c] = ffma2(a.x, w[j].x, acc[c]);
                    acc[c] = ffma2(a.y, w[j].y, acc[c]);
                }
            }
        }
        __syncthreads();
    }

    // epilogue: transpose via smem, coalesced partial store
    float* s_out = smem; // [NCOL][TM+1]
#pragma unroll
    for (int c=0;c<21;c++){
        float v = __uint_as_float((unsigned)acc[c]) + __uint_as_float((unsigned)(acc[c]>>32));
        s_out[(c0+c)*(TM+1) + r] = v;
    }
    __syncthreads();
    float* dst = g_part + (ks*NROWS + rowbase)*NCOL;
    for (int idx=tid; idx<TM*NCOL; idx+=GTHREADS){
        int row = idx / NCOL, col = idx % NCOL;
        dst[row*NCOL + col] = s_out[col*(TM+1) + row];
    }
}

// ---------------------------------------------------------------------------
// K3: row pass — reduce split-K, add biases, row LSEs, log-domain argmax
// operands transposed per class. One warp per row.
// ---------------------------------------------------------------------------
__global__ void __launch_bounds__(256) k_rowpass(const float* __restrict__ bcls,
                                                const float* __restrict__ br1,
                                                const float* __restrict__ br2,
                                                const float* __restrict__ isw){
    const unsigned FULL = 0xffffffffu;
    const int warp = threadIdx.x >> 5, lane = threadIdx.x & 31;
    const int n = blockIdx.x*8 + warp;
    const float NI = -1e38f;

    float v0, v1, v2 = 0.f;
    {
        float s = 0.f;
#pragma unroll
        for (int sp=0;sp<KSPLIT;sp++) s += g_part[(sp*NROWS+n)*NCOL + lane];
        s += (lane < 21) ? br1[lane] : br2[lane-21];
        v0 = s;
        g_scores[n*NCOL + lane] = s;
    }
    {
        int col = lane + 32;
        float s = 0.f;
#pragma unroll
        for (int sp=0;sp<KSPLIT;sp++) s += g_part[(sp*NROWS+n)*NCOL + col];
        if      (col < 42) s += br2[col-21];
        else if (col < 62) s += bcls[col-42];
        v1 = s;
        g_scores[n*NCOL + col] = s;
    }
    if (lane < 20){
        int col = lane + 64;
        float s = 0.f;
#pragma unroll
        for (int sp=0;sp<KSPLIT;sp++) s += g_part[(sp*NROWS+n)*NCOL + col];
        v2 = s;
        g_scores[n*NCOL + col] = s;
    }

    // lse over r1 block: cols 0..20
    float y = (lane <= 20) ? v0 : NI;
    float m1 = warp_max(y);
    float e = (lane <= 20) ? expf(v0 - m1) : 0.f;
    float lse1 = m1 + logf(warp_sum(e));

    // lse over r2 block: cols 21..41
    float ya = (lane >= 21) ? v0 : NI;
    float yb = (lane <= 9)  ? v1 : NI;
    float m2 = warp_max(fmaxf(ya, yb));
    e = ((lane >= 21) ? expf(v0 - m2) : 0.f) + ((lane <= 9) ? expf(v1 - m2) : 0.f);
    float lse2 = m2 + logf(warp_sum(e));

    // lse over cls block: cols 42..61
    y = (lane >= 10 && lane <= 29) ? v1 : NI;
    float mC = warp_max(y);
    e = (lane >= 10 && lane <= 29) ? expf(v1 - mC) : 0.f;
    float lseC = mC + logf(warp_sum(e));

    float lw = logf(isw[n]);
    if (lane == 0){ g_lse1[n] = lse1; g_lse2[n] = lse2; }

    // per-class extraction (class c = lane, c < 20)
    float clsv  = __shfl_sync(FULL, v1, (10 + lane) & 31);   // col 42+c
    float det_a = __shfl_sync(FULL, v1, 31);                 // col 63
    float det_b = __shfl_sync(FULL, v2, (lane + 31) & 31);   // col 64+(c-1)
    float detv  = (lane == 0) ? det_a : det_b;
    float r1v   = __shfl_sync(FULL, v0, (lane + 1) & 31);    // col 1+c

    if (lane < 20){
        int o = lane*NROWS + n;
        g_a1[o]   = clsv - lseC + detv + lw;  // log(cls_prob*det_prob*w) - const
        g_a2[o]   = r1v - lse1 + lw;          // log(refine_prob_1[:,c+1]*w)
        g_detT[o] = detv;
        g_clsT[o] = clsv;
    }
}

// ---------------------------------------------------------------------------
// K4: partial column pass. grid (NCH, CCLS): partial argmaxes + partial
// exp-sums (no max subtraction; |det| small).
// ---------------------------------------------------------------------------
__global__ void __launch_bounds__(256) k_colpassA(){
    __shared__ float sv[256];
    __shared__ int   si[256];
    const int ch = blockIdx.x, c = blockIdx.y, t = threadIdx.x;
    const int n0 = ch*CCHUNK;
    const float* a1 = g_a1   + c*NROWS;
    const float* a2 = g_a2   + c*NROWS;
    const float* dT = g_detT + c*NROWS;
    const float* cT = g_clsT + c*NROWS;

    float bv1=-1e38f, bv2=-1e38f, se=0.f, sc=0.f; int bi1=n0, bi2=n0;
    for (int n=n0+t; n<n0+CCHUNK; n+=256){
        float x = a1[n]; if (x > bv1){ bv1=x; bi1=n; }
        float z = a2[n]; if (z > bv2){ bv2=z; bi2=n; }
        float ex = expf(dT[n]);
        se += ex;
        sc += cT[n]*ex;
    }

    sv[t]=bv1; si[t]=bi1; __syncthreads();
    for (int s=128;s;s>>=1){
        if (t<s){ float ov=sv[t+s]; int oi=si[t+s];
            if (ov>sv[t] || (ov==sv[t] && oi<si[t])){ sv[t]=ov; si[t]=oi; } }
        __syncthreads();
    }
    if (t==0){ g_cpv1[c*NCH+ch]=sv[0]; g_cpi1[c*NCH+ch]=si[0]; }
    __syncthreads();

    sv[t]=bv2; si[t]=bi2; __syncthreads();
    for (int s=128;s;s>>=1){
        if (t<s){ float ov=sv[t+s]; int oi=si[t+s];
            if (ov>sv[t] || (ov==sv[t] && oi<si[t])){ sv[t]=ov; si[t]=oi; } }
        __syncthreads();
    }
    if (t==0){ g_cpv2[c*NCH+ch]=sv[0]; g_cpi2[c*NCH+ch]=si[0]; }
    __syncthreads();

    sv[t]=se; __syncthreads();
    for (int s=128;s;s>>=1){ if (t<s) sv[t]+=sv[t+s]; __syncthreads(); }
    if (t==0) g_cpse[c*NCH+ch]=sv[0];
    __syncthreads();

    sv[t]=sc; __syncthreads();
    for (int s=128;s;s>>=1){ if (t<s) sv[t]+=sv[t+s]; __syncthreads(); }
    if (t==0) g_cpsc[c*NCH+ch]=sv[0];
}

// ---------------------------------------------------------------------------
// K5: combine partials -> argmax boxes, detcls, hinge. 1 block, 32 threads.
// ---------------------------------------------------------------------------
__global__ void __launch_bounds__(32) k_combine(const float* __restrict__ ssb,
                                                const int* __restrict__ lbl){
    const int t = threadIdx.x;
    float h = 0.f;
    if (t < CCLS){
        float bv=-1e38f; int bi=0;
#pragma unroll
        for (int ch=0; ch<NCH; ch++){
            float v = g_cpv1[t*NCH+ch];
            if (v > bv){ bv=v; bi=g_cpi1[t*NCH+ch]; }
        }
        int i1 = bi;
        bv=-1e38f; bi=0;
#pragma unroll
        for (int ch=0; ch<NCH; ch++){
            float v = g_cpv2[t*NCH+ch];
            if (v > bv){ bv=v; bi=g_cpi2[t*NCH+ch]; }
        }
        int i2 = bi;
        float se=0.f, sc=0.f;
#pragma unroll
        for (int ch=0; ch<NCH; ch++){ se += g_cpse[t*NCH+ch]; sc += g_cpsc[t*NCH+ch]; }
        float dc = sc/se;

#pragma unroll
        for (int j=0;j<4;j++){ g_b1[t][j]=ssb[i1*5+1+j]; g_b2[t][j]=ssb[i2*5+1+j]; }
        g_ar1[t] = (g_b1[t][2]-g_b1[t][0]+1.f)*(g_b1[t][3]-g_b1[t][1]+1.f);
        g_ar2[t] = (g_b2[t][2]-g_b2[t][0]+1.f)*(g_b2[t][3]-g_b2[t][1]+1.f);
        g_pos[t] = (lbl[t] == 1);
        h = fmaxf(0.f, 1.f - (float)lbl[t]*dc);
    }
    h = warp_sum(h);
    if (t == 0) g_hinge = h / (float)CCLS;
}

// ---------------------------------------------------------------------------
// K6: IoU supervision partials. 32 blocks x 128 threads, 1 row per thread.
// ---------------------------------------------------------------------------
__global__ void __launch_bounds__(128) k_finalpartial(const float* __restrict__ ssb,
                                                      const float* __restrict__ isw){
    __shared__ float sb[FPR*5];
    __shared__ float swt[FPR];
    __shared__ float B1[CCLS][4], B2[CCLS][4], A1[CCLS], A2[CCLS];
    __shared__ int   P[CCLS];
    __shared__ float red[128];
    const int b = blockIdx.x, t = threadIdx.x;
    const int base = b*FPR;

    for (int i=t; i<FPR*5; i+=128) sb[i] = ssb[base*5 + i];
    swt[t] = isw[base+t];
    if (t < CCLS){
#pragma unroll
        for (int j=0;j<4;j++){ B1[t][j]=g_b1[t][j]; B2[t][j]=g_b2[t][j]; }
        A1[t]=g_ar1[t]; A2[t]=g_ar2[t]; P[t]=g_pos[t];
    }
    __syncthreads();

    const int n = base + t;
    float x0=sb[t*5+1], y0=sb[t*5+2], x1=sb[t*5+3], y1=sb[t*5+4];
    float ab = (x1-x0+1.f)*(y1-y0+1.f);
    float w = swt[t];
    float s1=0.f, c1=0.f, s2=0.f, c2=0.f;

    {
        float mo=-1e30f; int gt=0;
#pragma unroll
        for (int c=0;c<CCLS;c++){
            float ov = -1.f;
            if (P[c]){
                float xx1=fmaxf(x0,B1[c][0]), yy1=fmaxf(y0,B1[c][1]);
                float xx2=fminf(x1,B1[c][2]), yy2=fminf(y1,B1[c][3]);
                float iw=fmaxf(xx2-xx1+1.f,0.f), ih=fmaxf(yy2-yy1+1.f,0.f);
                float inter = iw*ih;
                ov = inter/(ab+A1[c]-inter);
            }
            if (ov > mo){ mo=ov; gt=c; }
        }
        bool fg = mo > 0.5f;
        if (fg || (mo >= 0.1f && mo < 0.5f)){
            int col = fg ? gt+1 : 0;
            s1 = w*(g_scores[n*NCOL + col] - g_lse1[n]);
            c1 = 1.f;
        }
    }
    {
        float mo=-1e30f; int gt=0;
#pragma unroll
        for (int c=0;c<CCLS;c++){
            float ov = -1.f;
            if (P[c]){
                float xx1=fmaxf(x0,B2[c][0]), yy1=fmaxf(y0,B2[c][1]);
                float xx2=fminf(x1,B2[c][2]), yy2=fminf(y1,B2[c][3]);
                float iw=fmaxf(xx2-xx1+1.f,0.f), ih=fmaxf(yy2-yy1+1.f,0.f);
                float inter = iw*ih;
                ov = inter/(ab+A2[c]-inter);
            }
            if (ov > mo){ mo=ov; gt=c; }
        }
        bool fg = mo > 0.5f;
        if (fg || (mo >= 0.1f && mo < 0.5f)){
            int col = fg ? gt+1 : 0;
            s2 = w*(g_scores[n*NCOL + 21 + col] - g_lse2[n]);
            c2 = 1.f;
        }
    }

    float vals[4] = {s1, c1, s2, c2};
#pragma unroll
    for (int j=0;j<4;j++){
        red[t]=vals[j]; __syncthreads();
        for (int s=64;s;s>>=1){ if (t<s) red[t]+=red[t+s]; __syncthreads(); }
        if (t==0) g_fp[b][j]=red[0];
        __syncthreads();
    }
}

// ---------------------------------------------------------------------------
// K7: final reduce -> scalar
// ---------------------------------------------------------------------------
__global__ void __launch_bounds__(32) k_final2(float* __restrict__ out){
    const int t = threadIdx.x;
    float s1 = warp_sum(g_fp[t][0]);
    float c1 = warp_sum(g_fp[t][1]);
    float s2 = warp_sum(g_fp[t][2]);
    float c2 = warp_sum(g_fp[t][3]);
    if (t == 0) out[0] = g_hinge + 0.1f*(-s1/c1 - s2/c2);
}

extern "C" void kernel_launch(void* const* d_in, const int* in_sizes, int n_in,
                              void* d_out, int out_size){
    const float* roi  = (const float*)d_in[0];
    const float* ctx  = (const float*)d_in[1];
    const float* frm  = (const float*)d_in[2];
    const float* Wcls = (const float*)d_in[3];
    const float* bcls = (const float*)d_in[4];
    const float* Wdet = (const float*)d_in[5];
    // d_in[6] = b_det: cancels in det_score
    const float* W1   = (const float*)d_in[7];
    const float* br1  = (const float*)d_in[8];
    const float* W2   = (const float*)d_in[9];
    const float* br2  = (const float*)d_in[10];
    const float* ssb  = (const float*)d_in[11];
    const float* isw  = (const float*)d_in[12];
    const int*   lbl  = (const int*)d_in[13];
    float* out = (float*)d_out;

    cudaFuncSetAttribute(k_gemm, cudaFuncAttributeMaxDynamicSharedMemorySize, SMEM_BYTES);

    k_transpose<<<128, 256>>>(Wcls, Wdet, W1, W2);    // idx 0
    k_nopA<<<1, 32>>>();                              // idx 1 (spacer: puts gemm at idx 3)
    k_nopB<<<1, 32>>>();                              // idx 2
    k_gemm<<<ROWBLOCKS*KSPLIT, GTHREADS, SMEM_BYTES>>>(roi, frm, ctx);  // idx 3 <- ncu capture
    k_rowpass<<<NROWS/8, 256>>>(bcls, br1, br2, isw);
    k_colpassA<<<dim3(NCH, CCLS), 256>>>();
    k_combine<<<1, 32>>>(ssb, lbl);
    k_finalpartial<<<FPB, 128>>>(ssb, isw);
    k_final2<<<1, 32>>>(out);
}

// round 11
// speedup vs baseline: 1.2090x; 1.2090x over previous
#include <cuda_runtime.h>
#include <cstdint>

#define NROWS 4096
#define FDIM  4096
#define NCOL  84      // [0,21) r1 | [21,42) r2 | [42,62) cls | 62 pad | [63,83) det | 83 pad
#define CCLS  20

#define TM 128
#define KC 32
#define KSPLIT 4
#define APITCH 36
#define WPITCH 32
#define GTHREADS 256
#define ROWBLOCKS (NROWS/TM)          // 32
#define KRANGE (FDIM/KSPLIT)          // 1024
#define NCHUNK (KRANGE/KC)            // 32

#define A_SZ (TM*APITCH)              // 4608 floats
#define W_SZ (NCOL*WPITCH)            // 2688 floats
#define STAGE_SZ (3*A_SZ + W_SZ)      // 16512 floats
#define SMEM_BYTES (2*STAGE_SZ*4)     // 132096 bytes

#define NCH  8                        // colpass chunks
#define CCHUNK (NROWS/NCH)            // 512
#define FPB  32                       // final-partial blocks
#define FPR  (NROWS/FPB)              // 128 rows per block

__device__ float g_Wt[NCOL*FDIM];
__device__ float g_part[KSPLIT*NROWS*NCOL];
__device__ float g_scores[NROWS*NCOL];
__device__ float g_lse1[NROWS];
__device__ float g_lse2[NROWS];
__device__ float g_a1[CCLS*NROWS];
__device__ float g_a2[CCLS*NROWS];
__device__ float g_detT[CCLS*NROWS];
__device__ float g_clsT[CCLS*NROWS];
// colpass partials
__device__ float g_cpv1[CCLS*NCH];
__device__ int   g_cpi1[CCLS*NCH];
__device__ float g_cpv2[CCLS*NCH];
__device__ int   g_cpi2[CCLS*NCH];
__device__ float g_cpse[CCLS*NCH];
__device__ float g_cpsc[CCLS*NCH];
// supervision boxes
__device__ float g_b1[CCLS][4];
__device__ float g_b2[CCLS][4];
__device__ float g_ar1[CCLS];
__device__ float g_ar2[CCLS];
__device__ int   g_pos[CCLS];
__device__ float g_hinge;
__device__ float g_fp[FPB][4];
__device__ float g_dummy[2];

__device__ __forceinline__ unsigned long long ffma2(unsigned long long a, unsigned long long b,
                                                    unsigned long long c){
    unsigned long long d;
    asm("fma.rn.f32x2 %0, %1, %2, %3;" : "=l"(d) : "l"(a), "l"(b), "l"(c));
    return d;
}

__device__ __forceinline__ void cpasync16(float* dst, const float* src){
    unsigned d = (unsigned)__cvta_generic_to_shared(dst);
    asm volatile("cp.async.cg.shared.global [%0], [%1], 16;" :: "r"(d), "l"(src));
}

__device__ __forceinline__ float warp_max(float v){
#pragma unroll
    for (int o=16;o;o>>=1) v = fmaxf(v, __shfl_xor_sync(0xffffffffu, v, o));
    return v;
}
__device__ __forceinline__ float warp_sum(float v){
#pragma unroll
    for (int o=16;o;o>>=1) v += __shfl_xor_sync(0xffffffffu, v, o);
    return v;
}

// ---------------------------------------------------------------------------
// K1: weight transpose/concat. 128 blocks = 4 sources x 32 k-chunks of 128.
// ---------------------------------------------------------------------------
__global__ void __launch_bounds__(256) k_transpose(const float* __restrict__ Wcls,
                                                   const float* __restrict__ Wdet,
                                                   const float* __restrict__ W1,
                                                   const float* __restrict__ W2){
    __shared__ float sm[21][132];
    int b = blockIdx.x;
    int src = b & 3, k0 = (b >> 2) * 128;
    const float* S; int ncols, cbase;
    if      (src==0){ S=W1;   ncols=21; cbase=0;  }
    else if (src==1){ S=W2;   ncols=21; cbase=21; }
    else if (src==2){ S=Wcls; ncols=20; cbase=42; }
    else            { S=Wdet; ncols=20; cbase=63; }
    int cnt = 128*ncols;
    for (int i=threadIdx.x; i<cnt; i+=256){
        float v = S[k0*ncols + i];
        sm[i%ncols][i/ncols] = v;
    }
    __syncthreads();
    for (int i=threadIdx.x; i<ncols*128; i+=256){
        int c = i>>7, kk = i&127;
        g_Wt[(cbase+c)*FDIM + k0 + kk] = sm[c][kk];
    }
}

// tiny spacer kernels so k_gemm lands at launch index 3 (where ncu captures)
__global__ void k_nopA(){ if (threadIdx.x==0) g_dummy[0] = 1.f; }
__global__ void k_nopB(){ if (threadIdx.x==0) g_dummy[1] = 1.f; }

// ---------------------------------------------------------------------------
// K2: fused GEMM. 128 blocks = 32 rowblocks x 4 ksplits. 256 thr = 4 groups
// of 64; group g owns 21 cols (g3 = det, frame-ctx fused); each thread owns
// rows r and r+64 -> W LDS amortized over 2 rows (halves L1 wavefronts).
// Packed f32x2 FMA; double-buffered cp.async; 3x7 W-blocking bounds live W
// regs at 28 (total live ~150 < 255 with launch_bounds(256,1): no spill).
// ---------------------------------------------------------------------------
__global__ void __launch_bounds__(GTHREADS,1)
k_gemm(const float* __restrict__ roi, const float* __restrict__ frm, const float* __restrict__ ctx){
    extern __shared__ float smem[];
    const int tid = threadIdx.x;
    const int q = tid >> 6;
    const int r = tid & 63;
    const int rowblk = blockIdx.x & (ROWBLOCKS-1);
    const int ks     = blockIdx.x / ROWBLOCKS;
    const int rowbase = rowblk * TM;
    const int kbase0  = ks * KRANGE;
    const int c0 = q * 21;

    unsigned long long acc0[21], acc1[21];
#pragma unroll
    for (int c=0;c<21;c++){ acc0[c]=0ull; acc1[c]=0ull; }

    auto issue_chunk = [&](int stage, int kglob){
        float* st = smem + stage*STAGE_SZ;
        float* s_roi = st;
        float* s_frm = st + A_SZ;
        float* s_ctx = st + 2*A_SZ;
        float* s_w   = st + 3*A_SZ;
#pragma unroll
        for (int i=0;i<4;i++){
            int s = tid + i*GTHREADS;
            int row = s >> 3, seg = s & 7;
            size_t goff = (size_t)(rowbase+row)*FDIM + kglob + seg*4;
            int soff = row*APITCH + seg*4;
            cpasync16(s_roi + soff, roi + goff);
            cpasync16(s_frm + soff, frm + goff);
            cpasync16(s_ctx + soff, ctx + goff);
        }
        for (int s = tid; s < NCOL*8; s += GTHREADS){
            int c = s >> 3, seg = s & 7;
            cpasync16(s_w + c*WPITCH + seg*4, g_Wt + c*FDIM + kglob + seg*4);
        }
    };

    issue_chunk(0, kbase0);
    asm volatile("cp.async.commit_group;");

    const unsigned long long NEG1 = 0xBF800000BF800000ull; // (-1.f, -1.f)

    for (int ch=0; ch<NCHUNK; ch++){
        if (ch+1 < NCHUNK){
            issue_chunk((ch+1)&1, kbase0 + (ch+1)*KC);
            asm volatile("cp.async.commit_group;");
            asm volatile("cp.async.wait_group 1;");
        } else {
            asm volatile("cp.async.wait_group 0;");
        }
        __syncthreads();

        const float* st = smem + (ch&1)*STAGE_SZ;
        const float* sA = (q==3) ? (st + A_SZ) : st;   // frame for det group, roi otherwise
        const float* sC = st + 2*A_SZ;
        const ulonglong2* a0p = reinterpret_cast<const ulonglong2*>(sA + r*APITCH);
        const ulonglong2* a1p = reinterpret_cast<const ulonglong2*>(sA + (r+64)*APITCH);
        const ulonglong2* e0p = reinterpret_cast<const ulonglong2*>(sC + r*APITCH);
        const ulonglong2* e1p = reinterpret_cast<const ulonglong2*>(sC + (r+64)*APITCH);
        const ulonglong2* wP  = reinterpret_cast<const ulonglong2*>(st + 3*A_SZ + c0*WPITCH);
#pragma unroll
        for (int k4=0;k4<KC/4;k4++){
            ulonglong2 a0 = a0p[k4];
            ulonglong2 a1 = a1p[k4];
            if (q==3){
                ulonglong2 c0v = e0p[k4], c1v = e1p[k4];
                a0.x = ffma2(c0v.x, NEG1, a0.x);
                a0.y = ffma2(c0v.y, NEG1, a0.y);
                a1.x = ffma2(c1v.x, NEG1, a1.x);
                a1.y = ffma2(c1v.y, NEG1, a1.y);
            }
            // 3 sub-blocks of 7 columns: bounds live W regs to 28
#pragma unroll
            for (int cb=0; cb<3; cb++){
                ulonglong2 w[7];
#pragma unroll
                for (int j=0;j<7;j++)
                    w[j] = wP[(cb*7 + j)*(WPITCH/4) + k4];
#pragma unroll
                for (int j=0;j<7;j++){
                    int c = cb*7 + j;
                    acc0[c] = ffma2(a0.x, w[j].x, acc0[c]);
                    acc0[c] = ffma2(a0.y, w[j].y, acc0[c]);
                    acc1[c] = ffma2(a1.x, w[j].x, acc1[c]);
                    acc1[c] = ffma2(a1.y, w[j].y, acc1[c]);
                }
            }
        }
        __syncthreads();
    }

    // epilogue: transpose via smem, coalesced partial store
    float* s_out = smem; // [NCOL][TM+1]
#pragma unroll
    for (int c=0;c<21;c++){
        float v0 = __uint_as_float((unsigned)acc0[c]) + __uint_as_float((unsigned)(acc0[c]>>32));
        float v1 = __uint_as_float((unsigned)acc1[c]) + __uint_as_float((unsigned)(acc1[c]>>32));
        s_out[(c0+c)*(TM+1) + r]      = v0;
        s_out[(c0+c)*(TM+1) + r + 64] = v1;
    }
    __syncthreads();
    float* dst = g_part + (ks*NROWS + rowbase)*NCOL;
    for (int idx=tid; idx<TM*NCOL; idx+=GTHREADS){
        int row = idx / NCOL, col = idx % NCOL;
        dst[row*NCOL + col] = s_out[col*(TM+1) + row];
    }
}

// ---------------------------------------------------------------------------
// K3: row pass — reduce split-K, add biases, row LSEs, log-domain argmax
// operands transposed per class. One warp per row.
// ---------------------------------------------------------------------------
__global__ void __launch_bounds__(256) k_rowpass(const float* __restrict__ bcls,
                                                const float* __restrict__ br1,
                                                const float* __restrict__ br2,
                                                const float* __restrict__ isw){
    const unsigned FULL = 0xffffffffu;
    const int warp = threadIdx.x >> 5, lane = threadIdx.x & 31;
    const int n = blockIdx.x*8 + warp;
    const float NI = -1e38f;

    float v0, v1, v2 = 0.f;
    {
        float s = 0.f;
#pragma unroll
        for (int sp=0;sp<KSPLIT;sp++) s += g_part[(sp*NROWS+n)*NCOL + lane];
        s += (lane < 21) ? br1[lane] : br2[lane-21];
        v0 = s;
        g_scores[n*NCOL + lane] = s;
    }
    {
        int col = lane + 32;
        float s = 0.f;
#pragma unroll
        for (int sp=0;sp<KSPLIT;sp++) s += g_part[(sp*NROWS+n)*NCOL + col];
        if      (col < 42) s += br2[col-21];
        else if (col < 62) s += bcls[col-42];
        v1 = s;
        g_scores[n*NCOL + col] = s;
    }
    if (lane < 20){
        int col = lane + 64;
        float s = 0.f;
#pragma unroll
        for (int sp=0;sp<KSPLIT;sp++) s += g_part[(sp*NROWS+n)*NCOL + col];
        v2 = s;
        g_scores[n*NCOL + col] = s;
    }

    // lse over r1 block: cols 0..20
    float y = (lane <= 20) ? v0 : NI;
    float m1 = warp_max(y);
    float e = (lane <= 20) ? expf(v0 - m1) : 0.f;
    float lse1 = m1 + logf(warp_sum(e));

    // lse over r2 block: cols 21..41
    float ya = (lane >= 21) ? v0 : NI;
    float yb = (lane <= 9)  ? v1 : NI;
    float m2 = warp_max(fmaxf(ya, yb));
    e = ((lane >= 21) ? expf(v0 - m2) : 0.f) + ((lane <= 9) ? expf(v1 - m2) : 0.f);
    float lse2 = m2 + logf(warp_sum(e));

    // lse over cls block: cols 42..61
    y = (lane >= 10 && lane <= 29) ? v1 : NI;
    float mC = warp_max(y);
    e = (lane >= 10 && lane <= 29) ? expf(v1 - mC) : 0.f;
    float lseC = mC + logf(warp_sum(e));

    float lw = logf(isw[n]);
    if (lane == 0){ g_lse1[n] = lse1; g_lse2[n] = lse2; }

    // per-class extraction (class c = lane, c < 20)
    float clsv  = __shfl_sync(FULL, v1, (10 + lane) & 31);   // col 42+c
    float det_a = __shfl_sync(FULL, v1, 31);                 // col 63
    float det_b = __shfl_sync(FULL, v2, (lane + 31) & 31);   // col 64+(c-1)
    float detv  = (lane == 0) ? det_a : det_b;
    float r1v   = __shfl_sync(FULL, v0, (lane + 1) & 31);    // col 1+c

    if (lane < 20){
        int o = lane*NROWS + n;
        g_a1[o]   = clsv - lseC + detv + lw;  // log(cls_prob*det_prob*w) - const
        g_a2[o]   = r1v - lse1 + lw;          // log(refine_prob_1[:,c+1]*w)
        g_detT[o] = detv;
        g_clsT[o] = clsv;
    }
}

// ---------------------------------------------------------------------------
// K4: partial column pass. grid (NCH, CCLS): partial argmaxes + partial
// exp-sums (no max subtraction; |det| small).
// ---------------------------------------------------------------------------
__global__ void __launch_bounds__(256) k_colpassA(){
    __shared__ float sv[256];
    __shared__ int   si[256];
    const int ch = blockIdx.x, c = blockIdx.y, t = threadIdx.x;
    const int n0 = ch*CCHUNK;
    const float* a1 = g_a1   + c*NROWS;
    const float* a2 = g_a2   + c*NROWS;
    const float* dT = g_detT + c*NROWS;
    const float* cT = g_clsT + c*NROWS;

    float bv1=-1e38f, bv2=-1e38f, se=0.f, sc=0.f; int bi1=n0, bi2=n0;
    for (int n=n0+t; n<n0+CCHUNK; n+=256){
        float x = a1[n]; if (x > bv1){ bv1=x; bi1=n; }
        float z = a2[n]; if (z > bv2){ bv2=z; bi2=n; }
        float ex = expf(dT[n]);
        se += ex;
        sc += cT[n]*ex;
    }

    sv[t]=bv1; si[t]=bi1; __syncthreads();
    for (int s=128;s;s>>=1){
        if (t<s){ float ov=sv[t+s]; int oi=si[t+s];
            if (ov>sv[t] || (ov==sv[t] && oi<si[t])){ sv[t]=ov; si[t]=oi; } }
        __syncthreads();
    }
    if (t==0){ g_cpv1[c*NCH+ch]=sv[0]; g_cpi1[c*NCH+ch]=si[0]; }
    __syncthreads();

    sv[t]=bv2; si[t]=bi2; __syncthreads();
    for (int s=128;s;s>>=1){
        if (t<s){ float ov=sv[t+s]; int oi=si[t+s];
            if (ov>sv[t] || (ov==sv[t] && oi<si[t])){ sv[t]=ov; si[t]=oi; } }
        __syncthreads();
    }
    if (t==0){ g_cpv2[c*NCH+ch]=sv[0]; g_cpi2[c*NCH+ch]=si[0]; }
    __syncthreads();

    sv[t]=se; __syncthreads();
    for (int s=128;s;s>>=1){ if (t<s) sv[t]+=sv[t+s]; __syncthreads(); }
    if (t==0) g_cpse[c*NCH+ch]=sv[0];
    __syncthreads();

    sv[t]=sc; __syncthreads();
    for (int s=128;s;s>>=1){ if (t<s) sv[t]+=sv[t+s]; __syncthreads(); }
    if (t==0) g_cpsc[c*NCH+ch]=sv[0];
}

// ---------------------------------------------------------------------------
// K5: combine partials -> argmax boxes, detcls, hinge. 1 block, 32 threads.
// ---------------------------------------------------------------------------
__global__ void __launch_bounds__(32) k_combine(const float* __restrict__ ssb,
                                                const int* __restrict__ lbl){
    const int t = threadIdx.x;
    float h = 0.f;
    if (t < CCLS){
        float bv=-1e38f; int bi=0;
#pragma unroll
        for (int ch=0; ch<NCH; ch++){
            float v = g_cpv1[t*NCH+ch];
            if (v > bv){ bv=v; bi=g_cpi1[t*NCH+ch]; }
        }
        int i1 = bi;
        bv=-1e38f; bi=0;
#pragma unroll
        for (int ch=0; ch<NCH; ch++){
            float v = g_cpv2[t*NCH+ch];
            if (v > bv){ bv=v; bi=g_cpi2[t*NCH+ch]; }
        }
        int i2 = bi;
        float se=0.f, sc=0.f;
#pragma unroll
        for (int ch=0; ch<NCH; ch++){ se += g_cpse[t*NCH+ch]; sc += g_cpsc[t*NCH+ch]; }
        float dc = sc/se;

#pragma unroll
        for (int j=0;j<4;j++){ g_b1[t][j]=ssb[i1*5+1+j]; g_b2[t][j]=ssb[i2*5+1+j]; }
        g_ar1[t] = (g_b1[t][2]-g_b1[t][0]+1.f)*(g_b1[t][3]-g_b1[t][1]+1.f);
        g_ar2[t] = (g_b2[t][2]-g_b2[t][0]+1.f)*(g_b2[t][3]-g_b2[t][1]+1.f);
        g_pos[t] = (lbl[t] == 1);
        h = fmaxf(0.f, 1.f - (float)lbl[t]*dc);
    }
    h = warp_sum(h);
    if (t == 0) g_hinge = h / (float)CCLS;
}

// ---------------------------------------------------------------------------
// K6: IoU supervision partials. 32 blocks x 128 threads, 1 row per thread.
// ---------------------------------------------------------------------------
__global__ void __launch_bounds__(128) k_finalpartial(const float* __restrict__ ssb,
                                                      const float* __restrict__ isw){
    __shared__ float sb[FPR*5];
    __shared__ float swt[FPR];
    __shared__ float B1[CCLS][4], B2[CCLS][4], A1[CCLS], A2[CCLS];
    __shared__ int   P[CCLS];
    __shared__ float red[128];
    const int b = blockIdx.x, t = threadIdx.x;
    const int base = b*FPR;

    for (int i=t; i<FPR*5; i+=128) sb[i] = ssb[base*5 + i];
    swt[t] = isw[base+t];
    if (t < CCLS){
#pragma unroll
        for (int j=0;j<4;j++){ B1[t][j]=g_b1[t][j]; B2[t][j]=g_b2[t][j]; }
        A1[t]=g_ar1[t]; A2[t]=g_ar2[t]; P[t]=g_pos[t];
    }
    __syncthreads();

    const int n = base + t;
    float x0=sb[t*5+1], y0=sb[t*5+2], x1=sb[t*5+3], y1=sb[t*5+4];
    float ab = (x1-x0+1.f)*(y1-y0+1.f);
    float w = swt[t];
    float s1=0.f, c1=0.f, s2=0.f, c2=0.f;

    {
        float mo=-1e30f; int gt=0;
#pragma unroll
        for (int c=0;c<CCLS;c++){
            float ov = -1.f;
            if (P[c]){
                float xx1=fmaxf(x0,B1[c][0]), yy1=fmaxf(y0,B1[c][1]);
                float xx2=fminf(x1,B1[c][2]), yy2=fminf(y1,B1[c][3]);
                float iw=fmaxf(xx2-xx1+1.f,0.f), ih=fmaxf(yy2-yy1+1.f,0.f);
                float inter = iw*ih;
                ov = inter/(ab+A1[c]-inter);
            }
            if (ov > mo){ mo=ov; gt=c; }
        }
        bool fg = mo > 0.5f;
        if (fg || (mo >= 0.1f && mo < 0.5f)){
            int col = fg ? gt+1 : 0;
            s1 = w*(g_scores[n*NCOL + col] - g_lse1[n]);
            c1 = 1.f;
        }
    }
    {
        float mo=-1e30f; int gt=0;
#pragma unroll
        for (int c=0;c<CCLS;c++){
            float ov = -1.f;
            if (P[c]){
                float xx1=fmaxf(x0,B2[c][0]), yy1=fmaxf(y0,B2[c][1]);
                float xx2=fminf(x1,B2[c][2]), yy2=fminf(y1,B2[c][3]);
                float iw=fmaxf(xx2-xx1+1.f,0.f), ih=fmaxf(yy2-yy1+1.f,0.f);
                float inter = iw*ih;
                ov = inter/(ab+A2[c]-inter);
            }
            if (ov > mo){ mo=ov; gt=c; }
        }
        bool fg = mo > 0.5f;
        if (fg || (mo >= 0.1f && mo < 0.5f)){
            int col = fg ? gt+1 : 0;
            s2 = w*(g_scores[n*NCOL + 21 + col] - g_lse2[n]);
            c2 = 1.f;
        }
    }

    float vals[4] = {s1, c1, s2, c2};
#pragma unroll
    for (int j=0;j<4;j++){
        red[t]=vals[j]; __syncthreads();
        for (int s=64;s;s>>=1){ if (t<s) red[t]+=red[t+s]; __syncthreads(); }
        if (t==0) g_fp[b][j]=red[0];
        __syncthreads();
    }
}

// ---------------------------------------------------------------------------
// K7: final reduce -> scalar
// ---------------------------------------------------------------------------
__global__ void __launch_bounds__(32) k_final2(float* __restrict__ out){
    const int t = threadIdx.x;
    float s1 = warp_sum(g_fp[t][0]);
    float c1 = warp_sum(g_fp[t][1]);
    float s2 = warp_sum(g_fp[t][2]);
    float c2 = warp_sum(g_fp[t][3]);
    if (t == 0) out[0] = g_hinge + 0.1f*(-s1/c1 - s2/c2);
}

extern "C" void kernel_launch(void* const* d_in, const int* in_sizes, int n_in,
                              void* d_out, int out_size){
    const float* roi  = (const float*)d_in[0];
    const float* ctx  = (const float*)d_in[1];
    const float* frm  = (const float*)d_in[2];
    const float* Wcls = (const float*)d_in[3];
    const float* bcls = (const float*)d_in[4];
    const float* Wdet = (const float*)d_in[5];
    // d_in[6] = b_det: cancels in det_score
    const float* W1   = (const float*)d_in[7];
    const float* br1  = (const float*)d_in[8];
    const float* W2   = (const float*)d_in[9];
    const float* br2  = (const float*)d_in[10];
    const float* ssb  = (const float*)d_in[11];
    const float* isw  = (const float*)d_in[12];
    const int*   lbl  = (const int*)d_in[13];
    float* out = (float*)d_out;

    cudaFuncSetAttribute(k_gemm, cudaFuncAttributeMaxDynamicSharedMemorySize, SMEM_BYTES);

    k_transpose<<<128, 256>>>(Wcls, Wdet, W1, W2);    // idx 0
    k_nopA<<<1, 32>>>();                              // idx 1 (spacer: puts gemm at idx 3)
    k_nopB<<<1, 32>>>();                              // idx 2
    k_gemm<<<ROWBLOCKS*KSPLIT, GTHREADS, SMEM_BYTES>>>(roi, frm, ctx);  // idx 3 <- ncu capture
    k_rowpass<<<NROWS/8, 256>>>(bcls, br1, br2, isw);
    k_colpassA<<<dim3(NCH, CCLS), 256>>>();
    k_combine<<<1, 32>>>(ssb, lbl);
    k_finalpartial<<<FPB, 128>>>(ssb, isw);
    k_final2<<<1, 32>>>(out);
}

// round 12
// speedup vs baseline: 1.2320x; 1.0189x over previous
#include <cuda_runtime.h>
#include <cstdint>

#define NROWS 4096
#define FDIM  4096
#define NCOL  84      // [0,21) r1 | [21,42) r2 | [42,62) cls | 62 pad | [63,83) det | 83 pad
#define CCLS  20

#define TM 128
#define KC 32
#define KSPLIT 4
#define APITCH 36
#define WPITCH 32
#define GTHREADS 256
#define ROWBLOCKS (NROWS/TM)          // 32
#define KRANGE (FDIM/KSPLIT)          // 1024
#define NCHUNK (KRANGE/KC)            // 32

#define A_SZ (TM*APITCH)              // 4608 floats
#define W_SZ (NCOL*WPITCH)            // 2688 floats
#define STAGE_SZ (3*A_SZ + W_SZ)      // 16512 floats
#define SMEM_BYTES (2*STAGE_SZ*4)     // 132096 bytes

#define NCH  8                        // colpass chunks
#define CCHUNK (NROWS/NCH)            // 512
#define FPB  32                       // final-partial blocks
#define FPR  (NROWS/FPB)              // 128 rows per block

__device__ float g_Wt[NCOL*FDIM];
__device__ float g_part[KSPLIT*NROWS*NCOL];
__device__ float g_scores[NROWS*NCOL];
__device__ float g_lse1[NROWS];
__device__ float g_lse2[NROWS];
__device__ float g_a1[CCLS*NROWS];
__device__ float g_a2[CCLS*NROWS];
__device__ float g_detT[CCLS*NROWS];
__device__ float g_clsT[CCLS*NROWS];
// colpass partials
__device__ float g_cpv1[CCLS*NCH];
__device__ int   g_cpi1[CCLS*NCH];
__device__ float g_cpv2[CCLS*NCH];
__device__ int   g_cpi2[CCLS*NCH];
__device__ float g_cpse[CCLS*NCH];
__device__ float g_cpsc[CCLS*NCH];
// supervision boxes
__device__ float g_b1[CCLS][4];
__device__ float g_b2[CCLS][4];
__device__ float g_ar1[CCLS];
__device__ float g_ar2[CCLS];
__device__ int   g_pos[CCLS];
__device__ float g_hinge;
__device__ float g_fp[FPB][4];
__device__ float g_dummy[2];

__device__ __forceinline__ unsigned long long ffma2(unsigned long long a, unsigned long long b,
                                                    unsigned long long c){
    unsigned long long d;
    asm("fma.rn.f32x2 %0, %1, %2, %3;" : "=l"(d) : "l"(a), "l"(b), "l"(c));
    return d;
}

__device__ __forceinline__ void cpasync16(float* dst, const float* src){
    unsigned d = (unsigned)__cvta_generic_to_shared(dst);
    asm volatile("cp.async.cg.shared.global [%0], [%1], 16;" :: "r"(d), "l"(src));
}

__device__ __forceinline__ float warp_max(float v){
#pragma unroll
    for (int o=16;o;o>>=1) v = fmaxf(v, __shfl_xor_sync(0xffffffffu, v, o));
    return v;
}
__device__ __forceinline__ float warp_sum(float v){
#pragma unroll
    for (int o=16;o;o>>=1) v += __shfl_xor_sync(0xffffffffu, v, o);
    return v;
}

// ---------------------------------------------------------------------------
// K1: weight transpose/concat. 128 blocks = 4 sources x 32 k-chunks of 128.
// ---------------------------------------------------------------------------
__global__ void __launch_bounds__(256) k_transpose(const float* __restrict__ Wcls,
                                                   const float* __restrict__ Wdet,
                                                   const float* __restrict__ W1,
                                                   const float* __restrict__ W2){
    __shared__ float sm[21][132];
    int b = blockIdx.x;
    int src = b & 3, k0 = (b >> 2) * 128;
    const float* S; int ncols, cbase;
    if      (src==0){ S=W1;   ncols=21; cbase=0;  }
    else if (src==1){ S=W2;   ncols=21; cbase=21; }
    else if (src==2){ S=Wcls; ncols=20; cbase=42; }
    else            { S=Wdet; ncols=20; cbase=63; }
    int cnt = 128*ncols;
    for (int i=threadIdx.x; i<cnt; i+=256){
        float v = S[k0*ncols + i];
        sm[i%ncols][i/ncols] = v;
    }
    __syncthreads();
    for (int i=threadIdx.x; i<ncols*128; i+=256){
        int c = i>>7, kk = i&127;
        g_Wt[(cbase+c)*FDIM + k0 + kk] = sm[c][kk];
    }
}

// tiny spacer kernels so k_gemm lands at launch index 3 (where ncu captures)
__global__ void k_nopA(){ if (threadIdx.x==0) g_dummy[0] = 1.f; }
__global__ void k_nopB(){ if (threadIdx.x==0) g_dummy[1] = 1.f; }

// ---------------------------------------------------------------------------
// K2: fused GEMM. 128 blocks = 32 rowblocks x 4 ksplits. 256 thr = 4 groups
// of 64; group g owns 21 cols (g3 = det, frame-ctx fused); each thread owns
// rows r and r+64. Explicit software pipelining: W sub-block and next-k4 A
// prefetched one step ahead so LDS latency (29cy) is covered at 2 warps/SMSP.
// ---------------------------------------------------------------------------
__global__ void __launch_bounds__(GTHREADS,1)
k_gemm(const float* __restrict__ roi, const float* __restrict__ frm, const float* __restrict__ ctx){
    extern __shared__ float smem[];
    const int tid = threadIdx.x;
    const int q = tid >> 6;
    const int r = tid & 63;
    const int rowblk = blockIdx.x & (ROWBLOCKS-1);
    const int ks     = blockIdx.x / ROWBLOCKS;
    const int rowbase = rowblk * TM;
    const int kbase0  = ks * KRANGE;
    const int c0 = q * 21;

    unsigned long long acc0[21], acc1[21];
#pragma unroll
    for (int c=0;c<21;c++){ acc0[c]=0ull; acc1[c]=0ull; }

    auto issue_chunk = [&](int stage, int kglob){
        float* st = smem + stage*STAGE_SZ;
        float* s_roi = st;
        float* s_frm = st + A_SZ;
        float* s_ctx = st + 2*A_SZ;
        float* s_w   = st + 3*A_SZ;
#pragma unroll
        for (int i=0;i<4;i++){
            int s = tid + i*GTHREADS;
            int row = s >> 3, seg = s & 7;
            size_t goff = (size_t)(rowbase+row)*FDIM + kglob + seg*4;
            int soff = row*APITCH + seg*4;
            cpasync16(s_roi + soff, roi + goff);
            cpasync16(s_frm + soff, frm + goff);
            cpasync16(s_ctx + soff, ctx + goff);
        }
        for (int s = tid; s < NCOL*8; s += GTHREADS){
            int c = s >> 3, seg = s & 7;
            cpasync16(s_w + c*WPITCH + seg*4, g_Wt + c*FDIM + kglob + seg*4);
        }
    };

    issue_chunk(0, kbase0);
    asm volatile("cp.async.commit_group;");

    const unsigned long long NEG1 = 0xBF800000BF800000ull; // (-1.f, -1.f)

    for (int ch=0; ch<NCHUNK; ch++){
        if (ch+1 < NCHUNK){
            issue_chunk((ch+1)&1, kbase0 + (ch+1)*KC);
            asm volatile("cp.async.commit_group;");
            asm volatile("cp.async.wait_group 1;");
        } else {
            asm volatile("cp.async.wait_group 0;");
        }
        __syncthreads();

        const float* st = smem + (ch&1)*STAGE_SZ;
        const float* sA = (q==3) ? (st + A_SZ) : st;   // frame for det group, roi otherwise
        const float* sC = st + 2*A_SZ;
        const ulonglong2* a0p = reinterpret_cast<const ulonglong2*>(sA + r*APITCH);
        const ulonglong2* a1p = reinterpret_cast<const ulonglong2*>(sA + (r+64)*APITCH);
        const ulonglong2* e0p = reinterpret_cast<const ulonglong2*>(sC + r*APITCH);
        const ulonglong2* e1p = reinterpret_cast<const ulonglong2*>(sC + (r+64)*APITCH);
        const ulonglong2* wP  = reinterpret_cast<const ulonglong2*>(st + 3*A_SZ + c0*WPITCH);

        // prologue: A(k4=0) with det fused, W(0,0)
        ulonglong2 a0 = a0p[0], a1 = a1p[0];
        if (q==3){
            ulonglong2 c0v = e0p[0], c1v = e1p[0];
            a0.x = ffma2(c0v.x, NEG1, a0.x);
            a0.y = ffma2(c0v.y, NEG1, a0.y);
            a1.x = ffma2(c1v.x, NEG1, a1.x);
            a1.y = ffma2(c1v.y, NEG1, a1.y);
        }
        ulonglong2 w[7];
#pragma unroll
        for (int j=0;j<7;j++) w[j] = wP[j*(WPITCH/4)];

#pragma unroll
        for (int k4=0;k4<KC/4;k4++){
            ulonglong2 a0n, a1n;
            if (k4+1 < KC/4){
                a0n = a0p[k4+1]; a1n = a1p[k4+1];
                if (q==3){
                    ulonglong2 c0v = e0p[k4+1], c1v = e1p[k4+1];
                    a0n.x = ffma2(c0v.x, NEG1, a0n.x);
                    a0n.y = ffma2(c0v.y, NEG1, a0n.y);
                    a1n.x = ffma2(c1v.x, NEG1, a1n.x);
                    a1n.y = ffma2(c1v.y, NEG1, a1n.y);
                }
            }
#pragma unroll
            for (int cb=0; cb<3; cb++){
                ulonglong2 wn[7];
                const bool last = (k4==KC/4-1) && (cb==2);
                if (!last){
                    const int nk4 = (cb<2) ? k4 : k4+1;
                    const int ncb = (cb<2) ? cb+1 : 0;
#pragma unroll
                    for (int j=0;j<7;j++)
                        wn[j] = wP[(ncb*7+j)*(WPITCH/4) + nk4];
                }
#pragma unroll
                for (int j=0;j<7;j++){
                    const int c = cb*7 + j;
                    acc0[c] = ffma2(a0.x, w[j].x, acc0[c]);
                    acc0[c] = ffma2(a0.y, w[j].y, acc0[c]);
                    acc1[c] = ffma2(a1.x, w[j].x, acc1[c]);
                    acc1[c] = ffma2(a1.y, w[j].y, acc1[c]);
                }
                if (!last){
#pragma unroll
                    for (int j=0;j<7;j++) w[j] = wn[j];
                }
            }
            if (k4+1 < KC/4){ a0 = a0n; a1 = a1n; }
        }
        __syncthreads();
    }

    // epilogue: transpose via smem, coalesced partial store
    float* s_out = smem; // [NCOL][TM+1]
#pragma unroll
    for (int c=0;c<21;c++){
        float v0 = __uint_as_float((unsigned)acc0[c]) + __uint_as_float((unsigned)(acc0[c]>>32));
        float v1 = __uint_as_float((unsigned)acc1[c]) + __uint_as_float((unsigned)(acc1[c]>>32));
        s_out[(c0+c)*(TM+1) + r]      = v0;
        s_out[(c0+c)*(TM+1) + r + 64] = v1;
    }
    __syncthreads();
    float* dst = g_part + (ks*NROWS + rowbase)*NCOL;
    for (int idx=tid; idx<TM*NCOL; idx+=GTHREADS){
        int row = idx / NCOL, col = idx % NCOL;
        dst[row*NCOL + col] = s_out[col*(TM+1) + row];
    }
}

// ---------------------------------------------------------------------------
// K3: row pass — reduce split-K, add biases, row LSEs, log-domain argmax
// operands transposed per class. One warp per row.
// ---------------------------------------------------------------------------
__global__ void __launch_bounds__(256) k_rowpass(const float* __restrict__ bcls,
                                                const float* __restrict__ br1,
                                                const float* __restrict__ br2,
                                                const float* __restrict__ isw){
    const unsigned FULL = 0xffffffffu;
    const int warp = threadIdx.x >> 5, lane = threadIdx.x & 31;
    const int n = blockIdx.x*8 + warp;
    const float NI = -1e38f;

    float v0, v1, v2 = 0.f;
    {
        float s = 0.f;
#pragma unroll
        for (int sp=0;sp<KSPLIT;sp++) s += g_part[(sp*NROWS+n)*NCOL + lane];
        s += (lane < 21) ? br1[lane] : br2[lane-21];
        v0 = s;
        g_scores[n*NCOL + lane] = s;
    }
    {
        int col = lane + 32;
        float s = 0.f;
#pragma unroll
        for (int sp=0;sp<KSPLIT;sp++) s += g_part[(sp*NROWS+n)*NCOL + col];
        if      (col < 42) s += br2[col-21];
        else if (col < 62) s += bcls[col-42];
        v1 = s;
        g_scores[n*NCOL + col] = s;
    }
    if (lane < 20){
        int col = lane + 64;
        float s = 0.f;
#pragma unroll
        for (int sp=0;sp<KSPLIT;sp++) s += g_part[(sp*NROWS+n)*NCOL + col];
        v2 = s;
        g_scores[n*NCOL + col] = s;
    }

    // lse over r1 block: cols 0..20
    float y = (lane <= 20) ? v0 : NI;
    float m1 = warp_max(y);
    float e = (lane <= 20) ? expf(v0 - m1) : 0.f;
    float lse1 = m1 + logf(warp_sum(e));

    // lse over r2 block: cols 21..41
    float ya = (lane >= 21) ? v0 : NI;
    float yb = (lane <= 9)  ? v1 : NI;
    float m2 = warp_max(fmaxf(ya, yb));
    e = ((lane >= 21) ? expf(v0 - m2) : 0.f) + ((lane <= 9) ? expf(v1 - m2) : 0.f);
    float lse2 = m2 + logf(warp_sum(e));

    // lse over cls block: cols 42..61
    y = (lane >= 10 && lane <= 29) ? v1 : NI;
    float mC = warp_max(y);
    e = (lane >= 10 && lane <= 29) ? expf(v1 - mC) : 0.f;
    float lseC = mC + logf(warp_sum(e));

    float lw = logf(isw[n]);
    if (lane == 0){ g_lse1[n] = lse1; g_lse2[n] = lse2; }

    // per-class extraction (class c = lane, c < 20)
    float clsv  = __shfl_sync(FULL, v1, (10 + lane) & 31);   // col 42+c
    float det_a = __shfl_sync(FULL, v1, 31);                 // col 63
    float det_b = __shfl_sync(FULL, v2, (lane + 31) & 31);   // col 64+(c-1)
    float detv  = (lane == 0) ? det_a : det_b;
    float r1v   = __shfl_sync(FULL, v0, (lane + 1) & 31);    // col 1+c

    if (lane < 20){
        int o = lane*NROWS + n;
        g_a1[o]   = clsv - lseC + detv + lw;  // log(cls_prob*det_prob*w) - const
        g_a2[o]   = r1v - lse1 + lw;          // log(refine_prob_1[:,c+1]*w)
        g_detT[o] = detv;
        g_clsT[o] = clsv;
    }
}

// ---------------------------------------------------------------------------
// K4: partial column pass. grid (NCH, CCLS): partial argmaxes + partial
// exp-sums (no max subtraction; |det| small).
// ---------------------------------------------------------------------------
__global__ void __launch_bounds__(256) k_colpassA(){
    __shared__ float sv[256];
    __shared__ int   si[256];
    const int ch = blockIdx.x, c = blockIdx.y, t = threadIdx.x;
    const int n0 = ch*CCHUNK;
    const float* a1 = g_a1   + c*NROWS;
    const float* a2 = g_a2   + c*NROWS;
    const float* dT = g_detT + c*NROWS;
    const float* cT = g_clsT + c*NROWS;

    float bv1=-1e38f, bv2=-1e38f, se=0.f, sc=0.f; int bi1=n0, bi2=n0;
    for (int n=n0+t; n<n0+CCHUNK; n+=256){
        float x = a1[n]; if (x > bv1){ bv1=x; bi1=n; }
        float z = a2[n]; if (z > bv2){ bv2=z; bi2=n; }
        float ex = expf(dT[n]);
        se += ex;
        sc += cT[n]*ex;
    }

    sv[t]=bv1; si[t]=bi1; __syncthreads();
    for (int s=128;s;s>>=1){
        if (t<s){ float ov=sv[t+s]; int oi=si[t+s];
            if (ov>sv[t] || (ov==sv[t] && oi<si[t])){ sv[t]=ov; si[t]=oi; } }
        __syncthreads();
    }
    if (t==0){ g_cpv1[c*NCH+ch]=sv[0]; g_cpi1[c*NCH+ch]=si[0]; }
    __syncthreads();

    sv[t]=bv2; si[t]=bi2; __syncthreads();
    for (int s=128;s;s>>=1){
        if (t<s){ float ov=sv[t+s]; int oi=si[t+s];
            if (ov>sv[t] || (ov==sv[t] && oi<si[t])){ sv[t]=ov; si[t]=oi; } }
        __syncthreads();
    }
    if (t==0){ g_cpv2[c*NCH+ch]=sv[0]; g_cpi2[c*NCH+ch]=si[0]; }
    __syncthreads();

    sv[t]=se; __syncthreads();
    for (int s=128;s;s>>=1){ if (t<s) sv[t]+=sv[t+s]; __syncthreads(); }
    if (t==0) g_cpse[c*NCH+ch]=sv[0];
    __syncthreads();

    sv[t]=sc; __syncthreads();
    for (int s=128;s;s>>=1){ if (t<s) sv[t]+=sv[t+s]; __syncthreads(); }
    if (t==0) g_cpsc[c*NCH+ch]=sv[0];
}

// ---------------------------------------------------------------------------
// K5: combine partials -> argmax boxes, detcls, hinge. 1 block, 32 threads.
// ---------------------------------------------------------------------------
__global__ void __launch_bounds__(32) k_combine(const float* __restrict__ ssb,
                                                const int* __restrict__ lbl){
    const int t = threadIdx.x;
    float h = 0.f;
    if (t < CCLS){
        float bv=-1e38f; int bi=0;
#pragma unroll
        for (int ch=0; ch<NCH; ch++){
            float v = g_cpv1[t*NCH+ch];
            if (v > bv){ bv=v; bi=g_cpi1[t*NCH+ch]; }
        }
        int i1 = bi;
        bv=-1e38f; bi=0;
#pragma unroll
        for (int ch=0; ch<NCH; ch++){
            float v = g_cpv2[t*NCH+ch];
            if (v > bv){ bv=v; bi=g_cpi2[t*NCH+ch]; }
        }
        int i2 = bi;
        float se=0.f, sc=0.f;
#pragma unroll
        for (int ch=0; ch<NCH; ch++){ se += g_cpse[t*NCH+ch]; sc += g_cpsc[t*NCH+ch]; }
        float dc = sc/se;

#pragma unroll
        for (int j=0;j<4;j++){ g_b1[t][j]=ssb[i1*5+1+j]; g_b2[t][j]=ssb[i2*5+1+j]; }
        g_ar1[t] = (g_b1[t][2]-g_b1[t][0]+1.f)*(g_b1[t][3]-g_b1[t][1]+1.f);
        g_ar2[t] = (g_b2[t][2]-g_b2[t][0]+1.f)*(g_b2[t][3]-g_b2[t][1]+1.f);
        g_pos[t] = (lbl[t] == 1);
        h = fmaxf(0.f, 1.f - (float)lbl[t]*dc);
    }
    h = warp_sum(h);
    if (t == 0) g_hinge = h / (float)CCLS;
}

// ---------------------------------------------------------------------------
// K6: IoU supervision partials. 32 blocks x 128 threads, 1 row per thread.
// ---------------------------------------------------------------------------
__global__ void __launch_bounds__(128) k_finalpartial(const float* __restrict__ ssb,
                                                      const float* __restrict__ isw){
    __shared__ float sb[FPR*5];
    __shared__ float swt[FPR];
    __shared__ float B1[CCLS][4], B2[CCLS][4], A1[CCLS], A2[CCLS];
    __shared__ int   P[CCLS];
    __shared__ float red[128];
    const int b = blockIdx.x, t = threadIdx.x;
    const int base = b*FPR;

    for (int i=t; i<FPR*5; i+=128) sb[i] = ssb[base*5 + i];
    swt[t] = isw[base+t];
    if (t < CCLS){
#pragma unroll
        for (int j=0;j<4;j++){ B1[t][j]=g_b1[t][j]; B2[t][j]=g_b2[t][j]; }
        A1[t]=g_ar1[t]; A2[t]=g_ar2[t]; P[t]=g_pos[t];
    }
    __syncthreads();

    const int n = base + t;
    float x0=sb[t*5+1], y0=sb[t*5+2], x1=sb[t*5+3], y1=sb[t*5+4];
    float ab = (x1-x0+1.f)*(y1-y0+1.f);
    float w = swt[t];
    float s1=0.f, c1=0.f, s2=0.f, c2=0.f;

    {
        float mo=-1e30f; int gt=0;
#pragma unroll
        for (int c=0;c<CCLS;c++){
            float ov = -1.f;
            if (P[c]){
                float xx1=fmaxf(x0,B1[c][0]), yy1=fmaxf(y0,B1[c][1]);
                float xx2=fminf(x1,B1[c][2]), yy2=fminf(y1,B1[c][3]);
                float iw=fmaxf(xx2-xx1+1.f,0.f), ih=fmaxf(yy2-yy1+1.f,0.f);
                float inter = iw*ih;
                ov = inter/(ab+A1[c]-inter);
            }
            if (ov > mo){ mo=ov; gt=c; }
        }
        bool fg = mo > 0.5f;
        if (fg || (mo >= 0.1f && mo < 0.5f)){
            int col = fg ? gt+1 : 0;
            s1 = w*(g_scores[n*NCOL + col] - g_lse1[n]);
            c1 = 1.f;
        }
    }
    {
        float mo=-1e30f; int gt=0;
#pragma unroll
        for (int c=0;c<CCLS;c++){
            float ov = -1.f;
            if (P[c]){
                float xx1=fmaxf(x0,B2[c][0]), yy1=fmaxf(y0,B2[c][1]);
                float xx2=fminf(x1,B2[c][2]), yy2=fminf(y1,B2[c][3]);
                float iw=fmaxf(xx2-xx1+1.f,0.f), ih=fmaxf(yy2-yy1+1.f,0.f);
                float inter = iw*ih;
                ov = inter/(ab+A2[c]-inter);
            }
            if (ov > mo){ mo=ov; gt=c; }
        }
        bool fg = mo > 0.5f;
        if (fg || (mo >= 0.1f && mo < 0.5f)){
            int col = fg ? gt+1 : 0;
            s2 = w*(g_scores[n*NCOL + 21 + col] - g_lse2[n]);
            c2 = 1.f;
        }
    }

    float vals[4] = {s1, c1, s2, c2};
#pragma unroll
    for (int j=0;j<4;j++){
        red[t]=vals[j]; __syncthreads();
        for (int s=64;s;s>>=1){ if (t<s) red[t]+=red[t+s]; __syncthreads(); }
        if (t==0) g_fp[b][j]=red[0];
        __syncthreads();
    }
}

// ---------------------------------------------------------------------------
// K7: final reduce -> scalar
// ---------------------------------------------------------------------------
__global__ void __launch_bounds__(32) k_final2(float* __restrict__ out){
    const int t = threadIdx.x;
    float s1 = warp_sum(g_fp[t][0]);
    float c1 = warp_sum(g_fp[t][1]);
    float s2 = warp_sum(g_fp[t][2]);
    float c2 = warp_sum(g_fp[t][3]);
    if (t == 0) out[0] = g_hinge + 0.1f*(-s1/c1 - s2/c2);
}

extern "C" void kernel_launch(void* const* d_in, const int* in_sizes, int n_in,
                              void* d_out, int out_size){
    const float* roi  = (const float*)d_in[0];
    const float* ctx  = (const float*)d_in[1];
    const float* frm  = (const float*)d_in[2];
    const float* Wcls = (const float*)d_in[3];
    const float* bcls = (const float*)d_in[4];
    const float* Wdet = (const float*)d_in[5];
    // d_in[6] = b_det: cancels in det_score
    const float* W1   = (const float*)d_in[7];
    const float* br1  = (const float*)d_in[8];
    const float* W2   = (const float*)d_in[9];
    const float* br2  = (const float*)d_in[10];
    const float* ssb  = (const float*)d_in[11];
    const float* isw  = (const float*)d_in[12];
    const int*   lbl  = (const int*)d_in[13];
    float* out = (float*)d_out;

    cudaFuncSetAttribute(k_gemm, cudaFuncAttributeMaxDynamicSharedMemorySize, SMEM_BYTES);

    k_transpose<<<128, 256>>>(Wcls, Wdet, W1, W2);    // idx 0
    k_nopA<<<1, 32>>>();                              // idx 1 (spacer: puts gemm at idx 3)
    k_nopB<<<1, 32>>>();                              // idx 2
    k_gemm<<<ROWBLOCKS*KSPLIT, GTHREADS, SMEM_BYTES>>>(roi, frm, ctx);  // idx 3 <- ncu capture
    k_rowpass<<<NROWS/8, 256>>>(bcls, br1, br2, isw);
    k_colpassA<<<dim3(NCH, CCLS), 256>>>();
    k_combine<<<1, 32>>>(ssb, lbl);
    k_finalpartial<<<FPB, 128>>>(ssb, isw);
    k_final2<<<1, 32>>>(out);
}